// round 12
// baseline (speedup 1.0000x reference)
#include <cuda_runtime.h>
#include <cuda_bf16.h>

#define GRID_N 4
#define WIN    3
#define NWIN   (GRID_N - WIN + 1)   // 2
#define NCELL  (GRID_N * GRID_N)    // 16
#define B_MAX  4096

// ---- Fast path constants (B=128, H=W=512) ----
#define NBATCH 128
#define NSTRIPE 512                 // 128 batches * 4 grid-rows

// Partials: [stripe][half(2)][gx(4)]. Unique writer per slot (no atomics).
__device__ float        g_part[NSTRIPE * 2 * 4];
__device__ unsigned int g_cnt[NBATCH];          // zero-init; reset each run
__device__ float        g_cell[B_MAX * NCELL];  // generic-fallback scratch

// 1024 CTAs x 128 threads, 8 CTAs/SM resident (all co-resident, wave 1).
// CTA = (b, gy, h): 64 rows x 512 cols = 8192 float4. Thread t reads
// float4 k*128 + t: column == t&127 -> gx = (t>>5)&3; warp w owns gx=w.
// Static 64-iter unrolled loop (proven R5/R9 shape), __ldcs streaming.
__global__ __launch_bounds__(128, 8) void fine_kernel(
        const float4* __restrict__ in, float* __restrict__ out) {
    int blk = blockIdx.x;
    int h   = blk & 1;
    int gy  = (blk >> 1) & 3;
    int b   = blk >> 3;
    int t   = threadIdx.x;

    const float4* base = in + (size_t)b * 65536 + gy * 16384 + h * 8192 + t;

    float acc = 0.0f;
#pragma unroll 16
    for (int k = 0; k < 64; k++) {
        float4 v = __ldcs(&base[k * 128]);
        acc += (v.x + v.y) + (v.z + v.w);
    }

#pragma unroll
    for (int o = 16; o > 0; o >>= 1)
        acc += __shfl_down_sync(0xffffffffu, acc, o);

    int stripe = b * 4 + gy;
    if ((t & 31) == 0)                              // lane 0 of warp w = gx w
        g_part[stripe * 8 + h * 4 + (t >> 5)] = acc;

    __syncthreads();                                // order stores < epilogue

    if (t == 0) {
        __threadfence();                            // publish partials
        unsigned old = atomicAdd(&g_cnt[b], 1u);    // 8 CTAs per batch
        if (old == 7u) {
            __threadfence();                        // acquire
            float c[NCELL];
#pragma unroll
            for (int gy2 = 0; gy2 < 4; gy2++)
#pragma unroll
                for (int gx = 0; gx < 4; gx++) {
                    int s8 = (b * 4 + gy2) * 8;
                    c[gy2 * 4 + gx] = __ldcg(&g_part[s8 + gx])
                                    + __ldcg(&g_part[s8 + 4 + gx]);
                }
            float win[NWIN * NWIN];
#pragma unroll
            for (int r = 0; r < NWIN; r++)
#pragma unroll
                for (int q = 0; q < NWIN; q++) {
                    float s = 0.0f;
#pragma unroll
                    for (int dr = 0; dr < WIN; dr++)
#pragma unroll
                        for (int dc = 0; dc < WIN; dc++)
                            s += c[(r + dr) * GRID_N + (q + dc)];
                    win[r * NWIN + q] = s;
                }
            float best = win[0];
            int bi = 0;
#pragma unroll
            for (int k2 = 1; k2 < NWIN * NWIN; k2++)
                if (win[k2] > best) { best = win[k2]; bi = k2; }

            out[b * 2 + 0] = (float)(bi >> 1);      // row (float32 output)
            out[b * 2 + 1] = (float)(bi & 1);       // col
            g_cnt[b] = 0u;                          // replay-safe reset
        }
    }
}

// ---------------- Generic fallback (any square H=W, H%4==0) ----------------
__global__ __launch_bounds__(256) void cell_sum_kernel(
        const float* __restrict__ in, int HW, int W, int gh, int gw) {
    int blk  = blockIdx.x;
    int cell = blk & (NCELL - 1);
    int b    = blk >> 4;
    int gx = cell & (GRID_N - 1);
    int gy = cell >> 2;
    const float* base = in + (size_t)b * HW + (size_t)(gy * gh) * W + (size_t)gx * gw;
    int t = threadIdx.x;
    int n = gh * gw;
    float acc = 0.0f;
    for (int i = t; i < n; i += 256) {
        int r = i / gw;
        int c = i - r * gw;
        acc += base[(size_t)r * W + c];
    }
    __shared__ float sh[256];
    sh[t] = acc;
    __syncthreads();
#pragma unroll
    for (int s = 128; s > 0; s >>= 1) {
        if (t < s) sh[t] += sh[t + s];
        __syncthreads();
    }
    if (t == 0) g_cell[blk] = sh[0];
}

__global__ void select_kernel(float* __restrict__ out, int B) {
    int b = blockIdx.x * blockDim.x + threadIdx.x;
    if (b >= B) return;
    float c[NCELL];
#pragma unroll
    for (int i = 0; i < NCELL; i++) c[i] = g_cell[b * NCELL + i];
    float win[NWIN * NWIN];
#pragma unroll
    for (int r = 0; r < NWIN; r++)
#pragma unroll
        for (int q = 0; q < NWIN; q++) {
            float s = 0.0f;
#pragma unroll
            for (int dr = 0; dr < WIN; dr++)
#pragma unroll
                for (int dc = 0; dc < WIN; dc++)
                    s += c[(r + dr) * GRID_N + (q + dc)];
            win[r * NWIN + q] = s;
        }
    float best = win[0];
    int bi = 0;
#pragma unroll
    for (int k = 1; k < NWIN * NWIN; k++)
        if (win[k] > best) { best = win[k]; bi = k; }
    out[b * 2 + 0] = (float)(bi / NWIN);
    out[b * 2 + 1] = (float)(bi % NWIN);
}

extern "C" void kernel_launch(void* const* d_in, const int* in_sizes, int n_in,
                              void* d_out, int out_size) {
    int best_i = 0;
    for (int i = 1; i < n_in; i++)
        if (in_sizes[i] > in_sizes[best_i]) best_i = i;
    const float* in = (const float*)d_in[best_i];
    float* out = (float*)d_out;

    int B = out_size / 2;
    if (B < 1) B = 1;
    long long HW = (long long)in_sizes[best_i] / B;

    if (B == NBATCH && HW == 512LL * 512LL) {
        fine_kernel<<<NBATCH * 8, 128>>>((const float4*)in, out);
    } else {
        if (B > B_MAX) B = B_MAX;
        int H = 1;
        while ((long long)(H + 1) * (H + 1) <= HW) H++;
        int W = H;
        cell_sum_kernel<<<B * NCELL, 256>>>(in, (int)HW, W, H / GRID_N, W / GRID_N);
        select_kernel<<<(B + 127) / 128, 128>>>(out, B);
    }
}

// round 13
// speedup vs baseline: 1.0115x; 1.0115x over previous
#include <cuda_runtime.h>
#include <cuda_bf16.h>

#define GRID_N 4
#define WIN    3
#define NWIN   (GRID_N - WIN + 1)   // 2
#define NCELL  (GRID_N * GRID_N)    // 16
#define B_MAX  4096

// 256-bit streaming load (sm_100+): LDG.E.256 evict-first.
__device__ __forceinline__ void ldcs_v8(const float* p,
        float& r0, float& r1, float& r2, float& r3,
        float& r4, float& r5, float& r6, float& r7) {
    asm volatile("ld.global.cs.v8.b32 {%0,%1,%2,%3,%4,%5,%6,%7}, [%8];"
        : "=f"(r0), "=f"(r1), "=f"(r2), "=f"(r3),
          "=f"(r4), "=f"(r5), "=f"(r6), "=f"(r7)
        : "l"(p));
}

// ---------------- Fast path: H = W = 512 (R9 structure, 256-bit loads) -----
// One block per batch, 1024 threads. Threads [64c, 64c+64) own cell c
// (gy=c/4, gx=c%4); each warp lies fully inside one cell. Cell = 128 rows
// x 16 float8 = 2048 float8; 64 threads -> 32 each. For i = k*64 + j:
// row = i>>4, c8 = i&15. Warp lanes 0-15 / 16-31 each cover one dense
// 512B row segment -> perfect coalescing at 1KB per warp-load.
__global__ __launch_bounds__(1024) void fused_512_kernel(
        const float* __restrict__ in, float* __restrict__ out) {
    int b = blockIdx.x;
    int t = threadIdx.x;
    int cell = t >> 6;
    int j    = t & 63;
    int gy = cell >> 2;
    int gx = cell & 3;

    // float strides: batch 262144, gy 65536, gx 128, row 512, c8 8
    const float* base = in + (size_t)b * 262144 + gy * 65536 + gx * 128;

    float a0 = 0.0f, a1 = 0.0f, a2 = 0.0f, a3 = 0.0f;
#pragma unroll 8
    for (int k = 0; k < 32; k++) {
        int i   = k * 64 + j;
        int row = i >> 4;
        int c8  = i & 15;
        float r0, r1, r2, r3, r4, r5, r6, r7;
        ldcs_v8(base + row * 512 + c8 * 8, r0, r1, r2, r3, r4, r5, r6, r7);
        a0 += r0 + r1;
        a1 += r2 + r3;
        a2 += r4 + r5;
        a3 += r6 + r7;
    }
    float acc = (a0 + a1) + (a2 + a3);

#pragma unroll
    for (int o = 16; o > 0; o >>= 1)
        acc += __shfl_down_sync(0xffffffffu, acc, o);

    __shared__ float wsum[32];
    if ((t & 31) == 0) wsum[t >> 5] = acc;
    __syncthreads();

    __shared__ float csum[NCELL];
    if (t < NCELL) csum[t] = wsum[2 * t] + wsum[2 * t + 1];
    __syncthreads();

    if (t == 0) {
        float win[NWIN * NWIN];
#pragma unroll
        for (int r = 0; r < NWIN; r++)
#pragma unroll
            for (int q = 0; q < NWIN; q++) {
                float s = 0.0f;
#pragma unroll
                for (int dr = 0; dr < WIN; dr++)
#pragma unroll
                    for (int dc = 0; dc < WIN; dc++)
                        s += csum[(r + dr) * GRID_N + (q + dc)];
                win[r * NWIN + q] = s;
            }
        float best = win[0];
        int bi = 0;
#pragma unroll
        for (int k = 1; k < NWIN * NWIN; k++)
            if (win[k] > best) { best = win[k]; bi = k; }

        out[b * 2 + 0] = (float)(bi >> 1);   // row (float32 output)
        out[b * 2 + 1] = (float)(bi & 1);    // col
    }
}

// ---------------- Generic fallback (any square H=W, H%4==0) ----------------
__device__ float g_cell[B_MAX * NCELL];

__global__ __launch_bounds__(256) void cell_sum_kernel(
        const float* __restrict__ in, int HW, int W, int gh, int gw) {
    int blk  = blockIdx.x;
    int cell = blk & (NCELL - 1);
    int b    = blk >> 4;
    int gx = cell & (GRID_N - 1);
    int gy = cell >> 2;

    const float* base = in + (size_t)b * HW + (size_t)(gy * gh) * W + (size_t)gx * gw;

    int t = threadIdx.x;
    int n = gh * gw;
    float acc = 0.0f;
    for (int i = t; i < n; i += 256) {
        int r = i / gw;
        int c = i - r * gw;
        acc += base[(size_t)r * W + c];
    }
    __shared__ float sh[256];
    sh[t] = acc;
    __syncthreads();
#pragma unroll
    for (int s = 128; s > 0; s >>= 1) {
        if (t < s) sh[t] += sh[t + s];
        __syncthreads();
    }
    if (t == 0) g_cell[blk] = sh[0];
}

__global__ void select_kernel(float* __restrict__ out, int B) {
    int b = blockIdx.x * blockDim.x + threadIdx.x;
    if (b >= B) return;
    float c[NCELL];
#pragma unroll
    for (int i = 0; i < NCELL; i++) c[i] = g_cell[b * NCELL + i];

    float win[NWIN * NWIN];
#pragma unroll
    for (int r = 0; r < NWIN; r++)
#pragma unroll
        for (int q = 0; q < NWIN; q++) {
            float s = 0.0f;
#pragma unroll
            for (int dr = 0; dr < WIN; dr++)
#pragma unroll
                for (int dc = 0; dc < WIN; dc++)
                    s += c[(r + dr) * GRID_N + (q + dc)];
            win[r * NWIN + q] = s;
        }
    float best = win[0];
    int bi = 0;
#pragma unroll
    for (int k = 1; k < NWIN * NWIN; k++)
        if (win[k] > best) { best = win[k]; bi = k; }

    out[b * 2 + 0] = (float)(bi / NWIN);
    out[b * 2 + 1] = (float)(bi % NWIN);
}

extern "C" void kernel_launch(void* const* d_in, const int* in_sizes, int n_in,
                              void* d_out, int out_size) {
    int best_i = 0;
    for (int i = 1; i < n_in; i++)
        if (in_sizes[i] > in_sizes[best_i]) best_i = i;
    const float* in = (const float*)d_in[best_i];
    float* out = (float*)d_out;

    int B = out_size / 2;
    if (B < 1) B = 1;
    long long HW = (long long)in_sizes[best_i] / B;

    if (HW == 512LL * 512LL) {
        fused_512_kernel<<<B, 1024>>>(in, out);
    } else {
        if (B > B_MAX) B = B_MAX;
        int H = 1;
        while ((long long)(H + 1) * (H + 1) <= HW) H++;
        int W = H;
        cell_sum_kernel<<<B * NCELL, 256>>>(in, (int)HW, W, H / GRID_N, W / GRID_N);
        select_kernel<<<(B + 127) / 128, 128>>>(out, B);
    }
}